// round 1
// baseline (speedup 1.0000x reference)
#include <cuda_runtime.h>

// out[i*2+0] = sum of edge_attr[e] for edges with edgeij_pair[0][e] == i
// out[i*2+1] = vertex_attr[i*2+1]

__global__ void init_out_kernel(const float* __restrict__ vattr,
                                float* __restrict__ out, int n_vertices) {
    int i = blockIdx.x * blockDim.x + threadIdx.x;
    if (i < n_vertices) {
        // vattr row i = {x, y}; out row i = {0, y}
        float2 v = reinterpret_cast<const float2*>(vattr)[i];
        float2 o;
        o.x = 0.0f;
        o.y = v.y;
        reinterpret_cast<float2*>(out)[i] = o;
    }
}

__global__ void scatter_add_kernel(const int* __restrict__ src_idx,
                                   const float* __restrict__ eattr,
                                   float* __restrict__ out, int n_edges) {
    int base = (blockIdx.x * blockDim.x + threadIdx.x) * 4;
    if (base + 3 < n_edges) {
        int4   vi = *reinterpret_cast<const int4*>(src_idx + base);
        float4 va = *reinterpret_cast<const float4*>(eattr + base);
        atomicAdd(out + 2 * vi.x, va.x);
        atomicAdd(out + 2 * vi.y, va.y);
        atomicAdd(out + 2 * vi.z, va.z);
        atomicAdd(out + 2 * vi.w, va.w);
    } else if (base < n_edges) {
        for (int e = base; e < n_edges; ++e) {
            atomicAdd(out + 2 * src_idx[e], eattr[e]);
        }
    }
}

extern "C" void kernel_launch(void* const* d_in, const int* in_sizes, int n_in,
                              void* d_out, int out_size) {
    // metadata order: vertex_attr [N,2] f32, edgeij_pair [2,E] i32,
    //                 edge_attr [E,1] f32, g [1,1] f32, batch [N] i32
    const float* vattr = (const float*)d_in[0];
    const int*   eij   = (const int*)d_in[1];
    const float* eattr = (const float*)d_in[2];
    float* out = (float*)d_out;

    int n_vertices = in_sizes[0] / 2;
    int n_edges    = in_sizes[2];
    const int* src_idx = eij; // row 0 of [2, E]

    {
        int threads = 256;
        int blocks = (n_vertices + threads - 1) / threads;
        init_out_kernel<<<blocks, threads>>>(vattr, out, n_vertices);
    }
    {
        int threads = 256;
        int per_block = threads * 4;
        int blocks = (n_edges + per_block - 1) / per_block;
        scatter_add_kernel<<<blocks, threads>>>(src_idx, eattr, out, n_edges);
    }
}